// round 1
// baseline (speedup 1.0000x reference)
#include <cuda_runtime.h>
#include <cstdint>

#define N_NODES  50000
#define N_EDGES  800000
#define N_GRAPHS 64
#define KDIM     256

// ---------------- device scratch (no allocs allowed) ----------------
__device__ float g_agg[N_NODES * 64];
__device__ float g_h0[N_NODES * 256];
__device__ float g_h1[N_NODES * 256];
__device__ float g_h2[N_NODES * 256];
__device__ float g_w1[256 * 256];
__device__ float g_w2[256 * 256];
__device__ float g_w3[256 * 128];

// round-to-nearest fp32 -> tf32 (keeps fp32 container, low mantissa bits zeroed)
__device__ __forceinline__ float tf32r(float x) {
    uint32_t u;
    asm("cvt.rna.tf32.f32 %0, %1;" : "=r"(u) : "f"(x));
    return __uint_as_float(u);
}

__device__ __forceinline__ void mma_tf32(float* c, const uint32_t* a, uint32_t b0, uint32_t b1) {
    asm volatile(
        "mma.sync.aligned.m16n8k8.row.col.f32.tf32.tf32.f32 "
        "{%0,%1,%2,%3}, {%4,%5,%6,%7}, {%8,%9}, {%0,%1,%2,%3};"
        : "+f"(c[0]), "+f"(c[1]), "+f"(c[2]), "+f"(c[3])
        : "r"(a[0]), "r"(a[1]), "r"(a[2]), "r"(a[3]), "r"(b0), "r"(b1));
}

// ---------------- kernel 1: zero agg ----------------
__global__ void zero_agg_kernel() {
    int idx = blockIdx.x * blockDim.x + threadIdx.x;  // float4 units
    const int total = N_NODES * 64 / 4;
    if (idx < total) {
        reinterpret_cast<float4*>(g_agg)[idx] = make_float4(0.f, 0.f, 0.f, 0.f);
    }
}

// ---------------- kernel 2: scatter-add edge_attr onto dest nodes ----------------
__global__ void scatter_kernel(const float* __restrict__ edge_attr,
                               const int* __restrict__ col) {
    int idx = blockIdx.x * blockDim.x + threadIdx.x;  // one float4 chunk of one edge
    if (idx >= N_EDGES * 16) return;
    int e = idx >> 4;
    int c = (idx & 15) << 2;
    int n = col[e];
    float4 v = *reinterpret_cast<const float4*>(edge_attr + (size_t)e * 64 + c);
    float* dst = g_agg + (size_t)n * 64 + c;
    atomicAdd(dst + 0, v.x);
    atomicAdd(dst + 1, v.y);
    atomicAdd(dst + 2, v.z);
    atomicAdd(dst + 3, v.w);
}

// ---------------- kernel 3: h0 = tf32round(concat[x, agg, u[batch]]) ----------------
__global__ void build_h0_kernel(const float* __restrict__ x,
                                const float* __restrict__ u,
                                const int* __restrict__ batch) {
    int idx = blockIdx.x * blockDim.x + threadIdx.x;
    if (idx >= N_NODES * 256) return;
    int i = idx >> 8;
    int j = idx & 255;
    float v;
    if (j < 128)      v = x[(size_t)i * 128 + j];
    else if (j < 192) v = g_agg[(size_t)i * 64 + (j - 128)];
    else              v = u[(size_t)batch[i] * 64 + (j - 192)];
    g_h0[idx] = tf32r(v);
}

// ---------------- kernel 4: round weights to tf32 ----------------
__global__ void round_w_kernel(const float* __restrict__ w1,
                               const float* __restrict__ w2,
                               const float* __restrict__ w3) {
    int i = blockIdx.x * blockDim.x + threadIdx.x;
    if (i < 65536)        g_w1[i] = tf32r(w1[i]);
    else if (i < 131072)  g_w2[i - 65536] = tf32r(w2[i - 65536]);
    else if (i < 163840)  g_w3[i - 131072] = tf32r(w3[i - 131072]);
}

// ---------------- GEMM: C[M,N] = act(A[M,256] @ W[256,N] + bias) ----------------
// BM=128 BN=128 BK=32, 256 threads = 8 warps (4 in M x 2 in N), warp tile 32x64
template <bool RELU, bool ROUND>
__global__ __launch_bounds__(256) void gemm_tf32_kernel(
    const float* __restrict__ A, const float* __restrict__ W,
    const float* __restrict__ bias, float* __restrict__ C,
    int M, int N) {
    __shared__ float As[128][36];  // [m][k], pad 4 (16B-aligned rows)
    __shared__ float Bs[128][36];  // [n][k]

    const int tid  = threadIdx.x;
    const int lane = tid & 31;
    const int warp = tid >> 5;
    const int wm = warp & 3;   // 0..3 -> m offset 32*wm
    const int wn = warp >> 2;  // 0..1 -> n offset 64*wn
    const int group = lane >> 2;  // 0..7
    const int thr   = lane & 3;   // 0..3

    const int m0 = blockIdx.x * 128;
    const int n0 = blockIdx.y * 128;

    float acc[2][8][4];
#pragma unroll
    for (int mi = 0; mi < 2; mi++)
#pragma unroll
        for (int ni = 0; ni < 8; ni++)
#pragma unroll
            for (int r = 0; r < 4; r++) acc[mi][ni][r] = 0.f;

    // A-load mapping: thread t -> row r=t/8 (+32*i), cols (t%8)*4..+3
    const int a_r  = tid >> 3;
    const int a_vc = (tid & 7) * 4;
    // B-load mapping: thread t -> n = t%128, k half = (t/128)*16
    const int b_n  = tid & 127;
    const int b_k0 = (tid >> 7) * 16;

    for (int kt = 0; kt < KDIM / 32; kt++) {
        const int k0 = kt * 32;
        // load A tile (guard M, zero-fill)
#pragma unroll
        for (int i = 0; i < 4; i++) {
            int row = a_r + i * 32;
            int gm = m0 + row;
            float4 v = make_float4(0.f, 0.f, 0.f, 0.f);
            if (gm < M) v = *reinterpret_cast<const float4*>(A + (size_t)gm * KDIM + k0 + a_vc);
            *reinterpret_cast<float4*>(&As[row][a_vc]) = v;
        }
        // load B tile transposed: Bs[n][k] = W[k0+k][n0+n]
#pragma unroll
        for (int kk = 0; kk < 16; kk++) {
            Bs[b_n][b_k0 + kk] = W[(size_t)(k0 + b_k0 + kk) * N + n0 + b_n];
        }
        __syncthreads();

#pragma unroll
        for (int ks = 0; ks < 4; ks++) {
            const int kk = ks * 8;
            uint32_t afrag[2][4];
#pragma unroll
            for (int mi = 0; mi < 2; mi++) {
                int row = wm * 32 + mi * 16;
                afrag[mi][0] = __float_as_uint(As[row + group][kk + thr]);
                afrag[mi][1] = __float_as_uint(As[row + group + 8][kk + thr]);
                afrag[mi][2] = __float_as_uint(As[row + group][kk + thr + 4]);
                afrag[mi][3] = __float_as_uint(As[row + group + 8][kk + thr + 4]);
            }
#pragma unroll
            for (int ni = 0; ni < 8; ni++) {
                int ncol = wn * 64 + ni * 8;
                uint32_t b0 = __float_as_uint(Bs[ncol + group][kk + thr]);
                uint32_t b1 = __float_as_uint(Bs[ncol + group][kk + thr + 4]);
#pragma unroll
                for (int mi = 0; mi < 2; mi++) mma_tf32(acc[mi][ni], afrag[mi], b0, b1);
            }
        }
        __syncthreads();
    }

    // epilogue
#pragma unroll
    for (int mi = 0; mi < 2; mi++) {
        int row_base = m0 + wm * 32 + mi * 16 + group;
#pragma unroll
        for (int ni = 0; ni < 8; ni++) {
            int nc = n0 + wn * 64 + ni * 8 + thr * 2;
            float bv0 = bias[nc];
            float bv1 = bias[nc + 1];
#pragma unroll
            for (int half = 0; half < 2; half++) {
                int row = row_base + half * 8;
                if (row < M) {
                    float v0 = acc[mi][ni][half * 2 + 0] + bv0;
                    float v1 = acc[mi][ni][half * 2 + 1] + bv1;
                    if (RELU) {
                        v0 = (v0 >= 0.f) ? v0 : 0.01f * v0;
                        v1 = (v1 >= 0.f) ? v1 : 0.01f * v1;
                    }
                    if (ROUND) { v0 = tf32r(v0); v1 = tf32r(v1); }
                    C[(size_t)row * N + nc]     = v0;
                    C[(size_t)row * N + nc + 1] = v1;
                }
            }
        }
    }
}

// ---------------- launch ----------------
extern "C" void kernel_launch(void* const* d_in, const int* in_sizes, int n_in,
                              void* d_out, int out_size) {
    const float* x          = (const float*)d_in[0];
    const int*   edge_index = (const int*)d_in[1];
    const float* edge_attr  = (const float*)d_in[2];
    const float* u          = (const float*)d_in[3];
    const int*   batch      = (const int*)d_in[4];
    const float* w1         = (const float*)d_in[5];
    const float* b1         = (const float*)d_in[6];
    const float* w2         = (const float*)d_in[7];
    const float* b2         = (const float*)d_in[8];
    const float* w3         = (const float*)d_in[9];
    const float* b3         = (const float*)d_in[10];
    float* out = (float*)d_out;

    float *pH0, *pH1, *pH2, *pW1, *pW2, *pW3;
    cudaGetSymbolAddress((void**)&pH0, g_h0);
    cudaGetSymbolAddress((void**)&pH1, g_h1);
    cudaGetSymbolAddress((void**)&pH2, g_h2);
    cudaGetSymbolAddress((void**)&pW1, g_w1);
    cudaGetSymbolAddress((void**)&pW2, g_w2);
    cudaGetSymbolAddress((void**)&pW3, g_w3);

    const int M = N_NODES;

    zero_agg_kernel<<<(N_NODES * 64 / 4 + 255) / 256, 256>>>();
    scatter_kernel<<<(N_EDGES * 16 + 255) / 256, 256>>>(edge_attr, edge_index + N_EDGES);
    round_w_kernel<<<(163840 + 255) / 256, 256>>>(w1, w2, w3);
    build_h0_kernel<<<(N_NODES * 256 + 255) / 256, 256>>>(x, u, batch);

    dim3 g1((M + 127) / 128, 2);
    gemm_tf32_kernel<true, true><<<g1, 256>>>(pH0, pW1, b1, pH1, M, 256);
    gemm_tf32_kernel<true, true><<<g1, 256>>>(pH1, pW2, b2, pH2, M, 256);
    dim3 g3((M + 127) / 128, 1);
    gemm_tf32_kernel<false, false><<<g3, 256>>>(pH2, pW3, b3, out, M, 128);
}

// round 2
// speedup vs baseline: 1.0060x; 1.0060x over previous
#include <cuda_runtime.h>
#include <cstdint>

#define N_NODES  50000
#define N_EDGES  800000
#define N_GRAPHS 64
#define KDIM     256

// ---------------- device scratch (no allocs allowed) ----------------
__device__ float g_agg[N_NODES * 64];
__device__ float g_h0[N_NODES * 256];
__device__ float g_h1[N_NODES * 256];
__device__ float g_h2[N_NODES * 256];
__device__ float g_w1[256 * 256];
__device__ float g_w2[256 * 256];
__device__ float g_w3[256 * 128];

// round-to-nearest fp32 -> tf32 (keeps fp32 container, low mantissa bits zeroed)
__device__ __forceinline__ float tf32r(float x) {
    uint32_t u;
    asm("cvt.rna.tf32.f32 %0, %1;" : "=r"(u) : "f"(x));
    return __uint_as_float(u);
}

__device__ __forceinline__ void mma_tf32(float* c, const uint32_t* a, uint32_t b0, uint32_t b1) {
    asm volatile(
        "mma.sync.aligned.m16n8k8.row.col.f32.tf32.tf32.f32 "
        "{%0,%1,%2,%3}, {%4,%5,%6,%7}, {%8,%9}, {%0,%1,%2,%3};"
        : "+f"(c[0]), "+f"(c[1]), "+f"(c[2]), "+f"(c[3])
        : "r"(a[0]), "r"(a[1]), "r"(a[2]), "r"(a[3]), "r"(b0), "r"(b1));
}

// ---------------- kernel 1: zero agg ----------------
__global__ void zero_agg_kernel() {
    int idx = blockIdx.x * blockDim.x + threadIdx.x;  // float4 units
    const int total = N_NODES * 64 / 4;
    if (idx < total) {
        reinterpret_cast<float4*>(g_agg)[idx] = make_float4(0.f, 0.f, 0.f, 0.f);
    }
}

// ---------------- kernel 2: scatter-add edge_attr onto dest nodes ----------------
__global__ void scatter_kernel(const float* __restrict__ edge_attr,
                               const int* __restrict__ col) {
    int idx = blockIdx.x * blockDim.x + threadIdx.x;  // one float4 chunk of one edge
    if (idx >= N_EDGES * 16) return;
    int e = idx >> 4;
    int c = (idx & 15) << 2;
    int n = col[e];
    float4 v = *reinterpret_cast<const float4*>(edge_attr + (size_t)e * 64 + c);
    float* dst = g_agg + (size_t)n * 64 + c;
    atomicAdd(dst + 0, v.x);
    atomicAdd(dst + 1, v.y);
    atomicAdd(dst + 2, v.z);
    atomicAdd(dst + 3, v.w);
}

// ---------------- kernel 3: h0 = tf32round(concat[x, agg, u[batch]]) ----------------
__global__ void build_h0_kernel(const float* __restrict__ x,
                                const float* __restrict__ u,
                                const int* __restrict__ batch) {
    int idx = blockIdx.x * blockDim.x + threadIdx.x;
    if (idx >= N_NODES * 256) return;
    int i = idx >> 8;
    int j = idx & 255;
    float v;
    if (j < 128)      v = x[(size_t)i * 128 + j];
    else if (j < 192) v = g_agg[(size_t)i * 64 + (j - 128)];
    else              v = u[(size_t)batch[i] * 64 + (j - 192)];
    g_h0[idx] = tf32r(v);
}

// ---------------- kernel 4: round weights to tf32 ----------------
__global__ void round_w_kernel(const float* __restrict__ w1,
                               const float* __restrict__ w2,
                               const float* __restrict__ w3) {
    int i = blockIdx.x * blockDim.x + threadIdx.x;
    if (i < 65536)        g_w1[i] = tf32r(w1[i]);
    else if (i < 131072)  g_w2[i - 65536] = tf32r(w2[i - 65536]);
    else if (i < 163840)  g_w3[i - 131072] = tf32r(w3[i - 131072]);
}

// ---------------- GEMM: C[M,N] = act(A[M,256] @ W[256,N] + bias) ----------------
// BM=128 BN=128 BK=32, 256 threads = 8 warps (4 in M x 2 in N), warp tile 32x64
template <bool RELU, bool ROUND>
__global__ __launch_bounds__(256) void gemm_tf32_kernel(
    const float* __restrict__ A, const float* __restrict__ W,
    const float* __restrict__ bias, float* __restrict__ C,
    int M, int N) {
    __shared__ float As[128][36];  // [m][k], pad 4 (16B-aligned rows)
    __shared__ float Bs[128][36];  // [n][k]

    const int tid  = threadIdx.x;
    const int lane = tid & 31;
    const int warp = tid >> 5;
    const int wm = warp & 3;   // 0..3 -> m offset 32*wm
    const int wn = warp >> 2;  // 0..1 -> n offset 64*wn
    const int group = lane >> 2;  // 0..7
    const int thr   = lane & 3;   // 0..3

    const int m0 = blockIdx.x * 128;
    const int n0 = blockIdx.y * 128;

    float acc[2][8][4];
#pragma unroll
    for (int mi = 0; mi < 2; mi++)
#pragma unroll
        for (int ni = 0; ni < 8; ni++)
#pragma unroll
            for (int r = 0; r < 4; r++) acc[mi][ni][r] = 0.f;

    // A-load mapping: thread t -> row r=t/8 (+32*i), cols (t%8)*4..+3
    const int a_r  = tid >> 3;
    const int a_vc = (tid & 7) * 4;
    // B-load mapping: thread t -> n = t%128, k half = (t/128)*16
    const int b_n  = tid & 127;
    const int b_k0 = (tid >> 7) * 16;

    for (int kt = 0; kt < KDIM / 32; kt++) {
        const int k0 = kt * 32;
        // load A tile (guard M, zero-fill)
#pragma unroll
        for (int i = 0; i < 4; i++) {
            int row = a_r + i * 32;
            int gm = m0 + row;
            float4 v = make_float4(0.f, 0.f, 0.f, 0.f);
            if (gm < M) v = *reinterpret_cast<const float4*>(A + (size_t)gm * KDIM + k0 + a_vc);
            *reinterpret_cast<float4*>(&As[row][a_vc]) = v;
        }
        // load B tile transposed: Bs[n][k] = W[k0+k][n0+n]
#pragma unroll
        for (int kk = 0; kk < 16; kk++) {
            Bs[b_n][b_k0 + kk] = W[(size_t)(k0 + b_k0 + kk) * N + n0 + b_n];
        }
        __syncthreads();

#pragma unroll
        for (int ks = 0; ks < 4; ks++) {
            const int kk = ks * 8;
            uint32_t afrag[2][4];
#pragma unroll
            for (int mi = 0; mi < 2; mi++) {
                int row = wm * 32 + mi * 16;
                afrag[mi][0] = __float_as_uint(As[row + group][kk + thr]);
                afrag[mi][1] = __float_as_uint(As[row + group + 8][kk + thr]);
                afrag[mi][2] = __float_as_uint(As[row + group][kk + thr + 4]);
                afrag[mi][3] = __float_as_uint(As[row + group + 8][kk + thr + 4]);
            }
#pragma unroll
            for (int ni = 0; ni < 8; ni++) {
                int ncol = wn * 64 + ni * 8;
                uint32_t b0 = __float_as_uint(Bs[ncol + group][kk + thr]);
                uint32_t b1 = __float_as_uint(Bs[ncol + group][kk + thr + 4]);
#pragma unroll
                for (int mi = 0; mi < 2; mi++) mma_tf32(acc[mi][ni], afrag[mi], b0, b1);
            }
        }
        __syncthreads();
    }

    // epilogue
#pragma unroll
    for (int mi = 0; mi < 2; mi++) {
        int row_base = m0 + wm * 32 + mi * 16 + group;
#pragma unroll
        for (int ni = 0; ni < 8; ni++) {
            int nc = n0 + wn * 64 + ni * 8 + thr * 2;
            float bv0 = bias[nc];
            float bv1 = bias[nc + 1];
#pragma unroll
            for (int half = 0; half < 2; half++) {
                int row = row_base + half * 8;
                if (row < M) {
                    float v0 = acc[mi][ni][half * 2 + 0] + bv0;
                    float v1 = acc[mi][ni][half * 2 + 1] + bv1;
                    if (RELU) {
                        v0 = (v0 >= 0.f) ? v0 : 0.01f * v0;
                        v1 = (v1 >= 0.f) ? v1 : 0.01f * v1;
                    }
                    if (ROUND) { v0 = tf32r(v0); v1 = tf32r(v1); }
                    C[(size_t)row * N + nc]     = v0;
                    C[(size_t)row * N + nc + 1] = v1;
                }
            }
        }
    }
}

// ---------------- launch ----------------
extern "C" void kernel_launch(void* const* d_in, const int* in_sizes, int n_in,
                              void* d_out, int out_size) {
    const float* x          = (const float*)d_in[0];
    const int*   edge_index = (const int*)d_in[1];
    const float* edge_attr  = (const float*)d_in[2];
    const float* u          = (const float*)d_in[3];
    const int*   batch      = (const int*)d_in[4];
    const float* w1         = (const float*)d_in[5];
    const float* b1         = (const float*)d_in[6];
    const float* w2         = (const float*)d_in[7];
    const float* b2         = (const float*)d_in[8];
    const float* w3         = (const float*)d_in[9];
    const float* b3         = (const float*)d_in[10];
    float* out = (float*)d_out;

    float *pH0, *pH1, *pH2, *pW1, *pW2, *pW3;
    cudaGetSymbolAddress((void**)&pH0, g_h0);
    cudaGetSymbolAddress((void**)&pH1, g_h1);
    cudaGetSymbolAddress((void**)&pH2, g_h2);
    cudaGetSymbolAddress((void**)&pW1, g_w1);
    cudaGetSymbolAddress((void**)&pW2, g_w2);
    cudaGetSymbolAddress((void**)&pW3, g_w3);

    const int M = N_NODES;

    zero_agg_kernel<<<(N_NODES * 64 / 4 + 255) / 256, 256>>>();
    scatter_kernel<<<(N_EDGES * 16 + 255) / 256, 256>>>(edge_attr, edge_index + N_EDGES);
    round_w_kernel<<<(163840 + 255) / 256, 256>>>(w1, w2, w3);
    build_h0_kernel<<<(N_NODES * 256 + 255) / 256, 256>>>(x, u, batch);

    dim3 g1((M + 127) / 128, 2);
    gemm_tf32_kernel<true, true><<<g1, 256>>>(pH0, pW1, b1, pH1, M, 256);
    gemm_tf32_kernel<true, true><<<g1, 256>>>(pH1, pW2, b2, pH2, M, 256);
    dim3 g3((M + 127) / 128, 1);
    gemm_tf32_kernel<false, false><<<g3, 256>>>(pH2, pW3, b3, out, M, 128);
}

// round 3
// speedup vs baseline: 1.5251x; 1.5160x over previous
#include <cuda_runtime.h>
#include <cstdint>

#define N_NODES  50000
#define N_EDGES  800000
#define KDIM     256
#define BM       128
#define THREADS  512
#define HSTR     260   // Ha row stride (floats): 256 + 4 pad -> conflict-free frag LDS

// ---------------- device scratch (no allocs allowed) ----------------
__device__ float g_agg[N_NODES * 64];
__device__ float g_w1[256 * 256];
__device__ float g_w2[256 * 256];
__device__ float g_w3[256 * 128];

// round-to-nearest fp32 -> tf32
__device__ __forceinline__ float tf32r(float x) {
    uint32_t u;
    asm("cvt.rna.tf32.f32 %0, %1;" : "=r"(u) : "f"(x));
    return __uint_as_float(u);
}

__device__ __forceinline__ void mma_tf32(float* c, const uint32_t* a, uint32_t b0, uint32_t b1) {
    asm volatile(
        "mma.sync.aligned.m16n8k8.row.col.f32.tf32.tf32.f32 "
        "{%0,%1,%2,%3}, {%4,%5,%6,%7}, {%8,%9}, {%0,%1,%2,%3};"
        : "+f"(c[0]), "+f"(c[1]), "+f"(c[2]), "+f"(c[3])
        : "r"(a[0]), "r"(a[1]), "r"(a[2]), "r"(a[3]), "r"(b0), "r"(b1));
}

__device__ __forceinline__ void cp16(uint32_t smem_dst, const void* gsrc) {
    asm volatile("cp.async.cg.shared.global [%0], [%1], 16;" :: "r"(smem_dst), "l"(gsrc));
}

// ---------------- kernel 1: zero agg ----------------
__global__ void zero_agg_kernel() {
    int idx = blockIdx.x * blockDim.x + threadIdx.x;
    const int total = N_NODES * 64 / 4;
    if (idx < total)
        reinterpret_cast<float4*>(g_agg)[idx] = make_float4(0.f, 0.f, 0.f, 0.f);
}

// ---------------- kernel 2: scatter-add with vector reductions ----------------
__global__ void scatter_kernel(const float* __restrict__ edge_attr,
                               const int* __restrict__ col) {
    int idx = blockIdx.x * blockDim.x + threadIdx.x;  // 4 threads per edge
    if (idx >= N_EDGES * 4) return;
    int e = idx >> 2;
    int c = (idx & 3) << 4;  // 16-float chunk
    int n = __ldg(col + e);
    const float4* src = reinterpret_cast<const float4*>(edge_attr + (size_t)e * 64 + c);
    float* dst = g_agg + (size_t)n * 64 + c;
#pragma unroll
    for (int j = 0; j < 4; j++) {
        float4 v = src[j];
        asm volatile("red.global.add.v4.f32 [%0], {%1,%2,%3,%4};"
                     :: "l"(dst + j * 4), "f"(v.x), "f"(v.y), "f"(v.z), "f"(v.w)
                     : "memory");
    }
}

// ---------------- kernel 3: round weights to tf32 ----------------
__global__ void round_w_kernel(const float* __restrict__ w1,
                               const float* __restrict__ w2,
                               const float* __restrict__ w3) {
    int i = blockIdx.x * blockDim.x + threadIdx.x;
    if (i < 65536)        g_w1[i] = tf32r(w1[i]);
    else if (i < 131072)  g_w2[i - 65536] = tf32r(w2[i - 65536]);
    else if (i < 163840)  g_w3[i - 131072] = tf32r(w3[i - 131072]);
}

// ---------------- fused 3-layer MLP: one block owns 128 rows for the whole depth ----
// Layer: C[128,N] = act(Ha[128,256] @ W[256,N] + bias); result written back to Ha
// (tf32-rounded) or to gmem for the last layer. Weights stream via cp.async
// double-buffer. 16 warps = 4(m) x 4(n); warp tile 32 x (N/4).
template <int N, bool RELU, bool TOGMEM>
__device__ __forceinline__ void mlp_layer(
    float* Ha, float* Wb, const float* __restrict__ Wg,
    const float* __restrict__ bias, float* __restrict__ outg,
    int m0, int tid) {
    constexpr int WSTR = N + 4;
    constexpr int NI = N / 32;                 // n8 tiles per warp: 8 or 4
    constexpr int TW = N / 4;                  // warp n-tile: 64 or 32
    constexpr int NCH = (32 * (N / 4)) / THREADS;  // cp.async float4 chunks/thread: 4 or 2

    const int lane = tid & 31, warp = tid >> 5;
    const int wm = warp & 3, wn = warp >> 2;
    const int group = lane >> 2, thr = lane & 3;
    const uint32_t wb_base = (uint32_t)__cvta_generic_to_shared(Wb);

    float acc[2][NI][4] = {};

    auto issue = [&](int kt) {
        int buf = kt & 1;
#pragma unroll
        for (int c = 0; c < NCH; c++) {
            int linear = tid + c * THREADS;
            int row = linear / (N / 4);
            int c4  = linear % (N / 4);
            cp16(wb_base + (uint32_t)((buf * 32 * WSTR + row * WSTR + c4 * 4) * 4),
                 Wg + (size_t)(kt * 32 + row) * N + c4 * 4);
        }
        asm volatile("cp.async.commit_group;");
    };

    issue(0);
    for (int kt = 0; kt < 8; kt++) {
        if (kt < 7) { issue(kt + 1); asm volatile("cp.async.wait_group 1;"); }
        else        { asm volatile("cp.async.wait_group 0;"); }
        __syncthreads();
        const float* Wt = Wb + (kt & 1) * 32 * WSTR;
#pragma unroll
        for (int ks = 0; ks < 4; ks++) {
            const int kk = ks * 8;
            const int kcol = kt * 32 + kk;
            uint32_t af[2][4];
#pragma unroll
            for (int mi = 0; mi < 2; mi++) {
                int r = wm * 32 + mi * 16;
                af[mi][0] = __float_as_uint(Ha[(r + group) * HSTR + kcol + thr]);
                af[mi][1] = __float_as_uint(Ha[(r + group + 8) * HSTR + kcol + thr]);
                af[mi][2] = __float_as_uint(Ha[(r + group) * HSTR + kcol + thr + 4]);
                af[mi][3] = __float_as_uint(Ha[(r + group + 8) * HSTR + kcol + thr + 4]);
            }
#pragma unroll
            for (int ni = 0; ni < NI; ni++) {
                int nc = wn * TW + ni * 8 + group;
                uint32_t b0 = __float_as_uint(Wt[(kk + thr) * WSTR + nc]);
                uint32_t b1 = __float_as_uint(Wt[(kk + thr + 4) * WSTR + nc]);
                mma_tf32(acc[0][ni], af[0], b0, b1);
                mma_tf32(acc[1][ni], af[1], b0, b1);
            }
        }
        __syncthreads();  // buffer reuse + (last iter) Ha-read completion barrier
    }

    // epilogue: bias + leakyrelu (+ tf32 round) -> Ha or gmem
#pragma unroll
    for (int mi = 0; mi < 2; mi++) {
#pragma unroll
        for (int ni = 0; ni < NI; ni++) {
            int nc = wn * TW + ni * 8 + thr * 2;
            float bv0 = bias[nc], bv1 = bias[nc + 1];
#pragma unroll
            for (int h = 0; h < 2; h++) {
                int rl = wm * 32 + mi * 16 + group + h * 8;
                float v0 = acc[mi][ni][h * 2 + 0] + bv0;
                float v1 = acc[mi][ni][h * 2 + 1] + bv1;
                if (RELU) {
                    v0 = (v0 >= 0.f) ? v0 : 0.01f * v0;
                    v1 = (v1 >= 0.f) ? v1 : 0.01f * v1;
                }
                if (TOGMEM) {
                    int gm = m0 + rl;
                    if (gm < N_NODES)
                        *reinterpret_cast<float2*>(outg + (size_t)gm * N + nc) =
                            make_float2(v0, v1);
                } else {
                    *reinterpret_cast<float2*>(&Ha[rl * HSTR + nc]) =
                        make_float2(tf32r(v0), tf32r(v1));
                }
            }
        }
    }
    if (!TOGMEM) __syncthreads();
}

__global__ __launch_bounds__(THREADS, 1) void fused_mlp_kernel(
    const float* __restrict__ x, const float* __restrict__ u,
    const int* __restrict__ batch,
    const float* __restrict__ b1, const float* __restrict__ b2,
    const float* __restrict__ b3, float* __restrict__ out) {
    extern __shared__ float sm[];
    float* Ha = sm;                   // 128 x 260
    float* Wb = sm + BM * HSTR;       // 2 x 32 x 260 (layer3 uses stride 132 inside)
    __shared__ int sb[BM];

    const int tid = threadIdx.x;
    const int m0 = blockIdx.x * BM;

    if (tid < BM) {
        int gm = m0 + tid;
        sb[tid] = (gm < N_NODES) ? batch[gm] : 0;
    }
    // h0 cols [0,128): x
#pragma unroll
    for (int i = 0; i < 8; i++) {
        int linear = tid + i * THREADS;     // 4096 float4s
        int row = linear >> 5, c4 = linear & 31;
        int gm = m0 + row;
        float4 v = make_float4(0.f, 0.f, 0.f, 0.f);
        if (gm < N_NODES) v = *reinterpret_cast<const float4*>(x + (size_t)gm * 128 + c4 * 4);
        v.x = tf32r(v.x); v.y = tf32r(v.y); v.z = tf32r(v.z); v.w = tf32r(v.w);
        *reinterpret_cast<float4*>(&Ha[row * HSTR + c4 * 4]) = v;
    }
    // h0 cols [128,192): agg
#pragma unroll
    for (int i = 0; i < 4; i++) {
        int linear = tid + i * THREADS;     // 2048 float4s
        int row = linear >> 4, c4 = linear & 15;
        int gm = m0 + row;
        float4 v = make_float4(0.f, 0.f, 0.f, 0.f);
        if (gm < N_NODES) v = *reinterpret_cast<const float4*>(g_agg + (size_t)gm * 64 + c4 * 4);
        v.x = tf32r(v.x); v.y = tf32r(v.y); v.z = tf32r(v.z); v.w = tf32r(v.w);
        *reinterpret_cast<float4*>(&Ha[row * HSTR + 128 + c4 * 4]) = v;
    }
    __syncthreads();  // sb ready
    // h0 cols [192,256): u[batch]
#pragma unroll
    for (int i = 0; i < 4; i++) {
        int linear = tid + i * THREADS;     // 2048 float4s
        int row = linear >> 4, c4 = linear & 15;
        float4 v = *reinterpret_cast<const float4*>(u + (size_t)sb[row] * 64 + c4 * 4);
        v.x = tf32r(v.x); v.y = tf32r(v.y); v.z = tf32r(v.z); v.w = tf32r(v.w);
        *reinterpret_cast<float4*>(&Ha[row * HSTR + 192 + c4 * 4]) = v;
    }
    __syncthreads();  // h0 ready

    mlp_layer<256, true,  false>(Ha, Wb, g_w1, b1, nullptr, m0, tid);
    mlp_layer<256, true,  false>(Ha, Wb, g_w2, b2, nullptr, m0, tid);
    mlp_layer<128, false, true >(Ha, Wb, g_w3, b3, out,     m0, tid);
}

// ---------------- launch ----------------
extern "C" void kernel_launch(void* const* d_in, const int* in_sizes, int n_in,
                              void* d_out, int out_size) {
    const float* x          = (const float*)d_in[0];
    const int*   edge_index = (const int*)d_in[1];
    const float* edge_attr  = (const float*)d_in[2];
    const float* u          = (const float*)d_in[3];
    const int*   batch      = (const int*)d_in[4];
    const float* w1         = (const float*)d_in[5];
    const float* b1         = (const float*)d_in[6];
    const float* w2         = (const float*)d_in[7];
    const float* b2         = (const float*)d_in[8];
    const float* w3         = (const float*)d_in[9];
    const float* b3         = (const float*)d_in[10];
    float* out = (float*)d_out;

    const int SMEM_BYTES = (BM * HSTR + 2 * 32 * HSTR) * 4;  // 199,680 B
    static bool attr_set = false;
    if (!attr_set) {
        cudaFuncSetAttribute(fused_mlp_kernel,
                             cudaFuncAttributeMaxDynamicSharedMemorySize, SMEM_BYTES);
        attr_set = true;
    }

    zero_agg_kernel<<<(N_NODES * 64 / 4 + 255) / 256, 256>>>();
    scatter_kernel<<<(N_EDGES * 4 + 255) / 256, 256>>>(edge_attr, edge_index + N_EDGES);
    round_w_kernel<<<(163840 + 255) / 256, 256>>>(w1, w2, w3);

    fused_mlp_kernel<<<(N_NODES + BM - 1) / BM, THREADS, SMEM_BYTES>>>(
        x, u, batch, b1, b2, b3, out);
}

// round 4
// speedup vs baseline: 1.8071x; 1.1849x over previous
#include <cuda_runtime.h>
#include <cstdint>

#define N_NODES  50000
#define N_EDGES  800000
#define KDIM     256
#define BM       128
#define THREADS  512
#define HSTR     272   // 256+16: 272 % 32 == 16 -> conflict-free A-frag LDS.128
#define EPB      128   // edges per scatter block

// ---------------- device scratch (no allocs allowed) ----------------
__device__ float g_agg[N_NODES * 64];
__device__ float g_w1[256 * 256];
__device__ float g_w2[256 * 256];
__device__ float g_w3[256 * 128];

// round-to-nearest fp32 -> tf32
__device__ __forceinline__ float tf32r(float x) {
    uint32_t u;
    asm("cvt.rna.tf32.f32 %0, %1;" : "=r"(u) : "f"(x));
    return __uint_as_float(u);
}

__device__ __forceinline__ void mma_tf32(float* c, const uint32_t* a, uint32_t b0, uint32_t b1) {
    asm volatile(
        "mma.sync.aligned.m16n8k8.row.col.f32.tf32.tf32.f32 "
        "{%0,%1,%2,%3}, {%4,%5,%6,%7}, {%8,%9}, {%0,%1,%2,%3};"
        : "+f"(c[0]), "+f"(c[1]), "+f"(c[2]), "+f"(c[3])
        : "r"(a[0]), "r"(a[1]), "r"(a[2]), "r"(a[3]), "r"(b0), "r"(b1));
}

__device__ __forceinline__ void cp16(uint32_t smem_dst, const void* gsrc) {
    asm volatile("cp.async.cg.shared.global [%0], [%1], 16;" :: "r"(smem_dst), "l"(gsrc));
}

// column permutation within each 16-col group: logical c = t + 4h + 8s  ->  4t + 2s + h
__device__ __forceinline__ int physcol(int c) {
    int w = c & 15;
    return (c & ~15) + ((w & 3) << 2) + (((w >> 3) & 1) << 1) + ((w >> 2) & 1);
}

// ---------------- kernel 1: zero agg ----------------
__global__ void zero_agg_kernel() {
    int idx = blockIdx.x * blockDim.x + threadIdx.x;
    const int total = N_NODES * 64 / 4;
    if (idx < total)
        reinterpret_cast<float4*>(g_agg)[idx] = make_float4(0.f, 0.f, 0.f, 0.f);
}

// ---------------- kernel 2: scatter via TMA bulk reduction ----------------
// Stage EPB edge rows in smem (cp.async), then one 256B bulk atomic-add per edge.
__global__ __launch_bounds__(256) void scatter_kernel(const float* __restrict__ edge_attr,
                                                      const int* __restrict__ col) {
    __shared__ float se[EPB * 64];
    __shared__ int   sc[EPB];
    const int tid = threadIdx.x;
    const long e0 = (long)blockIdx.x * EPB;

    if (tid < EPB) sc[tid] = col[e0 + tid];
    uint32_t sbase = (uint32_t)__cvta_generic_to_shared(se);
#pragma unroll
    for (int i = 0; i < 8; i++) {
        int l4 = tid + i * 256;  // 2048 float4 = EPB*64 floats (block reads contiguous 32KB)
        cp16(sbase + l4 * 16, edge_attr + e0 * 64 + l4 * 4);
    }
    asm volatile("cp.async.commit_group;");
    asm volatile("cp.async.wait_group 0;");
    __syncthreads();

    if (tid < EPB) {
        float* dst = g_agg + (size_t)sc[tid] * 64;
        asm volatile("cp.reduce.async.bulk.global.shared::cta.bulk_group.add.f32 [%0], [%1], %2;"
                     :: "l"(dst), "r"(sbase + tid * 256), "r"(256) : "memory");
        asm volatile("cp.async.bulk.commit_group;");
        asm volatile("cp.async.bulk.wait_group 0;");
    }
}

// ---------------- kernel 3: permute + tf32-round weights into fragment order ----
// Layout: idx = ((((kt*4 + wn)*4 + ks)*NP + p)*32 + lane)*4 + j
//   lane=(g,t); ni = 2p + (j>>1); kq = t + 4*(j&1)
//   value = W[kt*32 + ks*8 + kq][wn*(N/4) + ni*8 + g]
__device__ __forceinline__ void permute_one(const float* __restrict__ W, float* __restrict__ dst,
                                            int idx, int N) {
    const int NP = N / 64;
    int j = idx & 3;
    int lane = (idx >> 2) & 31;
    int r = idx >> 7;
    int p = r % NP;  r /= NP;
    int ks = r & 3;  r >>= 2;
    int wn = r & 3;
    int kt = r >> 2;
    int g = lane >> 2, t = lane & 3;
    int ni = 2 * p + (j >> 1);
    int kq = t + 4 * (j & 1);
    dst[idx] = tf32r(W[(size_t)(kt * 32 + ks * 8 + kq) * N + wn * (N / 4) + ni * 8 + g]);
}

__global__ void permute_w_kernel(const float* __restrict__ w1,
                                 const float* __restrict__ w2,
                                 const float* __restrict__ w3) {
    int i = blockIdx.x * blockDim.x + threadIdx.x;
    if (i < 65536)        permute_one(w1, g_w1, i, 256);
    else if (i < 131072)  permute_one(w2, g_w2, i - 65536, 256);
    else if (i < 163840)  permute_one(w3, g_w3, i - 131072, 128);
}

// ---------------- fused 3-layer MLP ----------------
// 16 warps = 4(m) x 4(n); warp tile 32 x (N/4). All fragment loads are LDS.128.
template <int N, bool RELU, bool TOGMEM>
__device__ __forceinline__ void mlp_layer(
    float* Ha, float* Wb, const float* __restrict__ Wg,
    const float* __restrict__ bias, float* __restrict__ outg,
    int m0, int tid) {
    constexpr int TW = N / 4;        // warp n-tile: 64 or 32
    constexpr int NI = N / 32;       // 8 or 4
    constexpr int NP = NI / 2;       // 4 or 2
    constexpr int CHUNK = 16 * NP * 128;      // floats per kt: 8192 / 4096
    constexpr int NCH = CHUNK / 4 / THREADS;  // cp.async float4 per thread: 4 / 2

    const int lane = tid & 31, warp = tid >> 5;
    const int wm = warp & 3, wn = warp >> 2;
    const int g = lane >> 2, t = lane & 3;
    const uint32_t wb_base = (uint32_t)__cvta_generic_to_shared(Wb);

    float acc[2][NI][4] = {};

    auto issue = [&](int kt) {
        int buf = kt & 1;
        const float* src = Wg + (size_t)kt * CHUNK;
#pragma unroll
        for (int c = 0; c < NCH; c++) {
            int l4 = tid + c * THREADS;
            cp16(wb_base + (uint32_t)((buf * CHUNK + l4 * 4) * 4), src + l4 * 4);
        }
        asm volatile("cp.async.commit_group;");
    };

    issue(0);
    for (int kt = 0; kt < 8; kt++) {
        if (kt < 7) { issue(kt + 1); asm volatile("cp.async.wait_group 1;"); }
        else        { asm volatile("cp.async.wait_group 0;"); }
        __syncthreads();
        const float* Wt = Wb + (kt & 1) * CHUNK;
#pragma unroll
        for (int kp = 0; kp < 2; kp++) {
            // A fragments for 2 k-steps: one LDS.128 per (mi, row-half)
            uint4 av[2][2];
#pragma unroll
            for (int mi = 0; mi < 2; mi++)
#pragma unroll
                for (int r = 0; r < 2; r++)
                    av[mi][r] = *reinterpret_cast<const uint4*>(
                        &Ha[(wm * 32 + mi * 16 + g + r * 8) * HSTR + kt * 32 + kp * 16 + t * 4]);
#pragma unroll
            for (int q = 0; q < 2; q++) {
                const int ks = kp * 2 + q;
                uint32_t afq[2][4];
#pragma unroll
                for (int mi = 0; mi < 2; mi++) {
                    afq[mi][0] = q ? av[mi][0].z : av[mi][0].x;
                    afq[mi][1] = q ? av[mi][1].z : av[mi][1].x;
                    afq[mi][2] = q ? av[mi][0].w : av[mi][0].y;
                    afq[mi][3] = q ? av[mi][1].w : av[mi][1].y;
                }
#pragma unroll
                for (int p = 0; p < NP; p++) {
                    uint4 bv = *reinterpret_cast<const uint4*>(
                        &Wt[(((wn * 4 + ks) * NP + p) * 32 + lane) * 4]);
                    mma_tf32(acc[0][2 * p],     afq[0], bv.x, bv.y);
                    mma_tf32(acc[1][2 * p],     afq[1], bv.x, bv.y);
                    mma_tf32(acc[0][2 * p + 1], afq[0], bv.z, bv.w);
                    mma_tf32(acc[1][2 * p + 1], afq[1], bv.z, bv.w);
                }
            }
        }
        __syncthreads();
    }

    // epilogue: bias + leakyrelu (+ tf32 round) -> Ha (permuted cols) or gmem (logical)
#pragma unroll
    for (int mi = 0; mi < 2; mi++) {
#pragma unroll
        for (int ni = 0; ni < NI; ni++) {
            int nc = wn * TW + ni * 8 + t * 2;
            float bv0 = bias[nc], bv1 = bias[nc + 1];
#pragma unroll
            for (int h = 0; h < 2; h++) {
                int rl = wm * 32 + mi * 16 + g + h * 8;
                float v0 = acc[mi][ni][h * 2 + 0] + bv0;
                float v1 = acc[mi][ni][h * 2 + 1] + bv1;
                if (RELU) {
                    v0 = (v0 >= 0.f) ? v0 : 0.01f * v0;
                    v1 = (v1 >= 0.f) ? v1 : 0.01f * v1;
                }
                if (TOGMEM) {
                    int gm = m0 + rl;
                    if (gm < N_NODES)
                        *reinterpret_cast<float2*>(outg + (size_t)gm * N + nc) =
                            make_float2(v0, v1);
                } else {
                    Ha[rl * HSTR + physcol(nc)]     = tf32r(v0);
                    Ha[rl * HSTR + physcol(nc + 1)] = tf32r(v1);
                }
            }
        }
    }
    if (!TOGMEM) __syncthreads();
}

__global__ __launch_bounds__(THREADS, 1) void fused_mlp_kernel(
    const float* __restrict__ x, const float* __restrict__ u,
    const int* __restrict__ batch,
    const float* __restrict__ b1, const float* __restrict__ b2,
    const float* __restrict__ b3, float* __restrict__ out) {
    extern __shared__ float sm[];
    float* Ha = sm;                   // 128 x 272 (col-pair-permuted)
    float* Wb = sm + BM * HSTR;       // 2 x 8192 (fragment-ordered weight chunks)
    __shared__ int sb[BM];

    const int tid = threadIdx.x;
    const int m0 = blockIdx.x * BM;

    if (tid < BM) {
        int gm = m0 + tid;
        sb[tid] = (gm < N_NODES) ? batch[gm] : 0;
    }
    // h0 cols [0,128): x
#pragma unroll
    for (int i = 0; i < 8; i++) {
        int linear = tid + i * THREADS;     // 4096 float4s
        int row = linear >> 5, c4 = linear & 31;
        int gm = m0 + row;
        float4 v = make_float4(0.f, 0.f, 0.f, 0.f);
        if (gm < N_NODES) v = *reinterpret_cast<const float4*>(x + (size_t)gm * 128 + c4 * 4);
        float* hr = Ha + row * HSTR;
        hr[physcol(4 * c4 + 0)] = tf32r(v.x);
        hr[physcol(4 * c4 + 1)] = tf32r(v.y);
        hr[physcol(4 * c4 + 2)] = tf32r(v.z);
        hr[physcol(4 * c4 + 3)] = tf32r(v.w);
    }
    // h0 cols [128,192): agg
#pragma unroll
    for (int i = 0; i < 4; i++) {
        int linear = tid + i * THREADS;     // 2048 float4s
        int row = linear >> 4, c4 = linear & 15;
        int gm = m0 + row;
        float4 v = make_float4(0.f, 0.f, 0.f, 0.f);
        if (gm < N_NODES) v = *reinterpret_cast<const float4*>(g_agg + (size_t)gm * 64 + c4 * 4);
        float* hr = Ha + row * HSTR;
        hr[physcol(128 + 4 * c4 + 0)] = tf32r(v.x);
        hr[physcol(128 + 4 * c4 + 1)] = tf32r(v.y);
        hr[physcol(128 + 4 * c4 + 2)] = tf32r(v.z);
        hr[physcol(128 + 4 * c4 + 3)] = tf32r(v.w);
    }
    __syncthreads();  // sb ready
    // h0 cols [192,256): u[batch]
#pragma unroll
    for (int i = 0; i < 4; i++) {
        int linear = tid + i * THREADS;     // 2048 float4s
        int row = linear >> 4, c4 = linear & 15;
        float4 v = *reinterpret_cast<const float4*>(u + (size_t)sb[row] * 64 + c4 * 4);
        float* hr = Ha + row * HSTR;
        hr[physcol(192 + 4 * c4 + 0)] = tf32r(v.x);
        hr[physcol(192 + 4 * c4 + 1)] = tf32r(v.y);
        hr[physcol(192 + 4 * c4 + 2)] = tf32r(v.z);
        hr[physcol(192 + 4 * c4 + 3)] = tf32r(v.w);
    }
    __syncthreads();  // h0 ready

    mlp_layer<256, true,  false>(Ha, Wb, g_w1, b1, nullptr, m0, tid);
    mlp_layer<256, true,  false>(Ha, Wb, g_w2, b2, nullptr, m0, tid);
    mlp_layer<128, false, true >(Ha, Wb, g_w3, b3, out,     m0, tid);
}

// ---------------- launch ----------------
extern "C" void kernel_launch(void* const* d_in, const int* in_sizes, int n_in,
                              void* d_out, int out_size) {
    const float* x          = (const float*)d_in[0];
    const int*   edge_index = (const int*)d_in[1];
    const float* edge_attr  = (const float*)d_in[2];
    const float* u          = (const float*)d_in[3];
    const int*   batch      = (const int*)d_in[4];
    const float* w1         = (const float*)d_in[5];
    const float* b1         = (const float*)d_in[6];
    const float* w2         = (const float*)d_in[7];
    const float* b2         = (const float*)d_in[8];
    const float* w3         = (const float*)d_in[9];
    const float* b3         = (const float*)d_in[10];
    float* out = (float*)d_out;

    const int SMEM_BYTES = (BM * HSTR + 2 * 8192) * 4;  // 204,800 B
    static bool attr_set = false;
    if (!attr_set) {
        cudaFuncSetAttribute(fused_mlp_kernel,
                             cudaFuncAttributeMaxDynamicSharedMemorySize, SMEM_BYTES);
        attr_set = true;
    }

    zero_agg_kernel<<<(N_NODES * 64 / 4 + 255) / 256, 256>>>();
    scatter_kernel<<<N_EDGES / EPB, 256>>>(edge_attr, edge_index + N_EDGES);
    permute_w_kernel<<<(163840 + 255) / 256, 256>>>(w1, w2, w3);

    fused_mlp_kernel<<<(N_NODES + BM - 1) / BM, THREADS, SMEM_BYTES>>>(
        x, u, batch, b1, b2, b3, out);
}

// round 5
// speedup vs baseline: 1.8331x; 1.0144x over previous
#include <cuda_runtime.h>
#include <cstdint>

#define N_NODES  50000
#define N_EDGES  800000
#define BM       64
#define THREADS  256
#define HSTR     272   // 256+16: g-row stride ≡16 mod 32 -> conflict-free LDS.128
#define EPB      128   // edges per scatter block

// ---------------- device scratch (no allocs allowed) ----------------
__device__ float g_agg[N_NODES * 64];
__device__ float g_w1[256 * 256];
__device__ float g_w2[256 * 256];
__device__ float g_w3[256 * 128];

// round-to-nearest fp32 -> tf32
__device__ __forceinline__ float tf32r(float x) {
    uint32_t u;
    asm("cvt.rna.tf32.f32 %0, %1;" : "=r"(u) : "f"(x));
    return __uint_as_float(u);
}

__device__ __forceinline__ void mma_tf32(float* c, const uint32_t* a, uint32_t b0, uint32_t b1) {
    asm volatile(
        "mma.sync.aligned.m16n8k8.row.col.f32.tf32.tf32.f32 "
        "{%0,%1,%2,%3}, {%4,%5,%6,%7}, {%8,%9}, {%0,%1,%2,%3};"
        : "+f"(c[0]), "+f"(c[1]), "+f"(c[2]), "+f"(c[3])
        : "r"(a[0]), "r"(a[1]), "r"(a[2]), "r"(a[3]), "r"(b0), "r"(b1));
}

__device__ __forceinline__ void cp16(uint32_t smem_dst, const void* gsrc) {
    asm volatile("cp.async.cg.shared.global [%0], [%1], 16;" :: "r"(smem_dst), "l"(gsrc));
}

// column permutation within each 16-col group: logical c = t + 4h + 8s -> 4t + 2s + h
__device__ __forceinline__ int physcol(int c) {
    int w = c & 15;
    return (c & ~15) + ((w & 3) << 2) + (((w >> 3) & 1) << 1) + ((w >> 2) & 1);
}

// ---------------- weight permute into per-kt fragment order ----------------
// chunk(kt) covers 16 k-rows; within chunk:
//   idx = (((wn*2 + ks)*NP + p)*32 + lane)*4 + j
//   row = kt*16 + ks*8 + t + 4*(j&1);  col = wn*(N/4) + (2p + (j>>1))*8 + g
__device__ __forceinline__ void permute_one(const float* __restrict__ W, float* __restrict__ dst,
                                            int idx, int N) {
    const int NP = N / 64;
    int j = idx & 3;
    int lane = (idx >> 2) & 31;
    int r = idx >> 7;
    int p = r % NP;  r /= NP;
    int ks = r & 1;  r >>= 1;
    int wn = r & 3;
    int kt = r >> 2;
    int g = lane >> 2, t = lane & 3;
    int row = kt * 16 + ks * 8 + t + 4 * (j & 1);
    int col = wn * (N / 4) + (2 * p + (j >> 1)) * 8 + g;
    dst[idx] = tf32r(W[(size_t)row * N + col]);
}

// ---------------- prep: zero agg + permute all weights (one launch) ----------
__global__ void prep_kernel(const float* __restrict__ w1,
                            const float* __restrict__ w2,
                            const float* __restrict__ w3) {
    int b = blockIdx.x;
    if (b < 3125) {  // zero g_agg: 800000 float4
        int idx = b * 256 + threadIdx.x;
        reinterpret_cast<float4*>(g_agg)[idx] = make_float4(0.f, 0.f, 0.f, 0.f);
    } else {         // permute weights: 163840 elements
        int i = (b - 3125) * 256 + threadIdx.x;
        if (i < 65536)        permute_one(w1, g_w1, i, 256);
        else if (i < 131072)  permute_one(w2, g_w2, i - 65536, 256);
        else                  permute_one(w3, g_w3, i - 131072, 128);
    }
}

// ---------------- scatter via TMA bulk reduction ----------------
__global__ __launch_bounds__(256) void scatter_kernel(const float* __restrict__ edge_attr,
                                                      const int* __restrict__ col) {
    __shared__ float se[EPB * 64];
    __shared__ int   sc[EPB];
    const int tid = threadIdx.x;
    const long e0 = (long)blockIdx.x * EPB;

    if (tid < EPB) sc[tid] = col[e0 + tid];
    uint32_t sbase = (uint32_t)__cvta_generic_to_shared(se);
#pragma unroll
    for (int i = 0; i < 8; i++) {
        int l4 = tid + i * 256;
        cp16(sbase + l4 * 16, edge_attr + e0 * 64 + l4 * 4);
    }
    asm volatile("cp.async.commit_group;");
    asm volatile("cp.async.wait_group 0;");
    __syncthreads();

    if (tid < EPB) {
        float* dst = g_agg + (size_t)sc[tid] * 64;
        asm volatile("cp.reduce.async.bulk.global.shared::cta.bulk_group.add.f32 [%0], [%1], %2;"
                     :: "l"(dst), "r"(sbase + tid * 256), "r"(256) : "memory");
        asm volatile("cp.async.bulk.commit_group;");
        asm volatile("cp.async.bulk.wait_group 0;");
    }
}

// ---------------- fused 3-layer MLP, BM=64 / 8 warps / 2 CTAs per SM ----------
// warps: wm = warp&1 (2 m-tiles of 32), wn = warp>>1 (4 n-tiles of N/4)
template <int N, bool RELU, bool TOGMEM>
__device__ __forceinline__ void mlp_layer(
    float* Ha, float* Wb, const float* __restrict__ Wg,
    const float* __restrict__ bias, float* __restrict__ outg,
    int m0, int tid) {
    constexpr int TW = N / 4;        // warp n-tile: 64 or 32
    constexpr int NI = N / 32;       // 8 or 4
    constexpr int NP = NI / 2;       // 4 or 2
    constexpr int CHUNK = 16 * N;    // floats per kt chunk (16 k-rows)
    constexpr int NCH = CHUNK / 4 / THREADS;  // float4 cp.async per thread

    const int lane = tid & 31, warp = tid >> 5;
    const int wm = warp & 1, wn = warp >> 1;
    const int g = lane >> 2, t = lane & 3;
    const uint32_t wb_base = (uint32_t)__cvta_generic_to_shared(Wb);

    float acc[2][NI][4] = {};

    auto issue = [&](int kt) {
        int buf = kt & 1;
        const float* src = Wg + (size_t)kt * CHUNK;
#pragma unroll
        for (int c = 0; c < NCH; c++) {
            int l4 = tid + c * THREADS;
            cp16(wb_base + (uint32_t)((buf * CHUNK + l4 * 4) * 4), src + l4 * 4);
        }
        asm volatile("cp.async.commit_group;");
    };

    issue(0);
    for (int kt = 0; kt < 16; kt++) {
        asm volatile("cp.async.wait_group 0;");
        __syncthreads();              // buf[kt&1] ready; prior iter's reads done
        if (kt < 15) issue(kt + 1);   // safe: overwrites buf read 2 iters ago
        const float* Wt = Wb + (kt & 1) * CHUNK;

        // A fragments (2 k-steps each): one LDS.128 per (mi, row-half)
        uint4 av[2][2];
#pragma unroll
        for (int mi = 0; mi < 2; mi++)
#pragma unroll
            for (int r = 0; r < 2; r++)
                av[mi][r] = *reinterpret_cast<const uint4*>(
                    &Ha[(wm * 32 + mi * 16 + g + r * 8) * HSTR + kt * 16 + t * 4]);
#pragma unroll
        for (int ks = 0; ks < 2; ks++) {
            uint32_t afq[2][4];
#pragma unroll
            for (int mi = 0; mi < 2; mi++) {
                afq[mi][0] = ks ? av[mi][0].z : av[mi][0].x;
                afq[mi][1] = ks ? av[mi][1].z : av[mi][1].x;
                afq[mi][2] = ks ? av[mi][0].w : av[mi][0].y;
                afq[mi][3] = ks ? av[mi][1].w : av[mi][1].y;
            }
#pragma unroll
            for (int p = 0; p < NP; p++) {
                uint4 bv = *reinterpret_cast<const uint4*>(
                    &Wt[(((wn * 2 + ks) * NP + p) * 32 + lane) * 4]);
                mma_tf32(acc[0][2 * p],     afq[0], bv.x, bv.y);
                mma_tf32(acc[1][2 * p],     afq[1], bv.x, bv.y);
                mma_tf32(acc[0][2 * p + 1], afq[0], bv.z, bv.w);
                mma_tf32(acc[1][2 * p + 1], afq[1], bv.z, bv.w);
            }
        }
    }
    __syncthreads();  // all reads of Ha done before epilogue rewrites it

    // epilogue: bias + leakyrelu (+ tf32 round) -> Ha (permuted cols) or gmem
#pragma unroll
    for (int mi = 0; mi < 2; mi++) {
#pragma unroll
        for (int ni = 0; ni < NI; ni++) {
            int nc = wn * TW + ni * 8 + t * 2;
            float bv0 = bias[nc], bv1 = bias[nc + 1];
#pragma unroll
            for (int h = 0; h < 2; h++) {
                int rl = wm * 32 + mi * 16 + g + h * 8;
                float v0 = acc[mi][ni][h * 2 + 0] + bv0;
                float v1 = acc[mi][ni][h * 2 + 1] + bv1;
                if (RELU) {
                    v0 = (v0 >= 0.f) ? v0 : 0.01f * v0;
                    v1 = (v1 >= 0.f) ? v1 : 0.01f * v1;
                }
                if (TOGMEM) {
                    int gm = m0 + rl;
                    if (gm < N_NODES)
                        *reinterpret_cast<float2*>(outg + (size_t)gm * N + nc) =
                            make_float2(v0, v1);
                } else {
                    Ha[rl * HSTR + physcol(nc)]     = tf32r(v0);
                    Ha[rl * HSTR + physcol(nc + 1)] = tf32r(v1);
                }
            }
        }
    }
    if (!TOGMEM) __syncthreads();
}

__global__ __launch_bounds__(THREADS, 2) void fused_mlp_kernel(
    const float* __restrict__ x, const float* __restrict__ u,
    const int* __restrict__ batch,
    const float* __restrict__ b1, const float* __restrict__ b2,
    const float* __restrict__ b3, float* __restrict__ out) {
    extern __shared__ float sm[];
    float* Ha = sm;                   // 64 x 272 (col-pair-permuted)
    float* Wb = sm + BM * HSTR;       // 2 x 4096 weight chunk ring
    __shared__ int sb[BM];

    const int tid = threadIdx.x;
    const int m0 = blockIdx.x * BM;

    if (tid < BM) {
        int gm = m0 + tid;
        sb[tid] = (gm < N_NODES) ? batch[gm] : 0;
    }
    // h0 cols [0,128): x  (2048 float4)
#pragma unroll
    for (int i = 0; i < 8; i++) {
        int linear = tid + i * THREADS;
        int row = linear >> 5, c4 = linear & 31;
        int gm = m0 + row;
        float4 v = make_float4(0.f, 0.f, 0.f, 0.f);
        if (gm < N_NODES) v = *reinterpret_cast<const float4*>(x + (size_t)gm * 128 + c4 * 4);
        float* hr = Ha + row * HSTR;
        hr[physcol(4 * c4 + 0)] = tf32r(v.x);
        hr[physcol(4 * c4 + 1)] = tf32r(v.y);
        hr[physcol(4 * c4 + 2)] = tf32r(v.z);
        hr[physcol(4 * c4 + 3)] = tf32r(v.w);
    }
    // h0 cols [128,192): agg  (1024 float4)
#pragma unroll
    for (int i = 0; i < 4; i++) {
        int linear = tid + i * THREADS;
        int row = linear >> 4, c4 = linear & 15;
        int gm = m0 + row;
        float4 v = make_float4(0.f, 0.f, 0.f, 0.f);
        if (gm < N_NODES) v = *reinterpret_cast<const float4*>(g_agg + (size_t)gm * 64 + c4 * 4);
        float* hr = Ha + row * HSTR;
        hr[physcol(128 + 4 * c4 + 0)] = tf32r(v.x);
        hr[physcol(128 + 4 * c4 + 1)] = tf32r(v.y);
        hr[physcol(128 + 4 * c4 + 2)] = tf32r(v.z);
        hr[physcol(128 + 4 * c4 + 3)] = tf32r(v.w);
    }
    __syncthreads();  // sb ready
    // h0 cols [192,256): u[batch]  (1024 float4)
#pragma unroll
    for (int i = 0; i < 4; i++) {
        int linear = tid + i * THREADS;
        int row = linear >> 4, c4 = linear & 15;
        float4 v = *reinterpret_cast<const float4*>(u + (size_t)sb[row] * 64 + c4 * 4);
        float* hr = Ha + row * HSTR;
        hr[physcol(192 + 4 * c4 + 0)] = tf32r(v.x);
        hr[physcol(192 + 4 * c4 + 1)] = tf32r(v.y);
        hr[physcol(192 + 4 * c4 + 2)] = tf32r(v.z);
        hr[physcol(192 + 4 * c4 + 3)] = tf32r(v.w);
    }
    __syncthreads();  // h0 ready

    mlp_layer<256, true,  false>(Ha, Wb, g_w1, b1, nullptr, m0, tid);
    mlp_layer<256, true,  false>(Ha, Wb, g_w2, b2, nullptr, m0, tid);
    mlp_layer<128, false, true >(Ha, Wb, g_w3, b3, out,     m0, tid);
}

// ---------------- launch ----------------
extern "C" void kernel_launch(void* const* d_in, const int* in_sizes, int n_in,
                              void* d_out, int out_size) {
    const float* x          = (const float*)d_in[0];
    const int*   edge_index = (const int*)d_in[1];
    const float* edge_attr  = (const float*)d_in[2];
    const float* u          = (const float*)d_in[3];
    const int*   batch      = (const int*)d_in[4];
    const float* w1         = (const float*)d_in[5];
    const float* b1         = (const float*)d_in[6];
    const float* w2         = (const float*)d_in[7];
    const float* b2         = (const float*)d_in[8];
    const float* w3         = (const float*)d_in[9];
    const float* b3         = (const float*)d_in[10];
    float* out = (float*)d_out;

    const int SMEM_BYTES = (BM * HSTR + 2 * 4096) * 4;  // 102,400 B -> 2 CTAs/SM
    static bool attr_set = false;
    if (!attr_set) {
        cudaFuncSetAttribute(fused_mlp_kernel,
                             cudaFuncAttributeMaxDynamicSharedMemorySize, SMEM_BYTES);
        attr_set = true;
    }

    prep_kernel<<<3125 + 640, 256>>>(w1, w2, w3);
    scatter_kernel<<<N_EDGES / EPB, 256>>>(edge_attr, edge_index + N_EDGES);

    fused_mlp_kernel<<<(N_NODES + BM - 1) / BM, THREADS, SMEM_BYTES>>>(
        x, u, batch, b1, b2, b3, out);
}

// round 8
// speedup vs baseline: 2.7814x; 1.5174x over previous
#include <cuda_runtime.h>
#include <cuda_fp16.h>
#include <cstdint>

#define N_NODES  50000
#define N_EDGES  800000
#define BM       64
#define THREADS  256
#define ASTR     576     // A row stride bytes: 16B-aligned; 576/4=144 ≡16 mod 32 -> conflict-free LDS.128
#define EPB      128

// ---------------- device scratch (no allocs allowed) ----------------
__device__ float  g_agg[N_NODES * 64];
__device__ __half g_w1h[256 * 256];
__device__ __half g_w2h[256 * 256];
__device__ __half g_w3h[256 * 128];

// ---------------- helpers ----------------
__device__ __forceinline__ void cp16(uint32_t smem_dst, const void* gsrc) {
    asm volatile("cp.async.cg.shared.global [%0], [%1], 16;" :: "r"(smem_dst), "l"(gsrc));
}
__device__ __forceinline__ uint4 lds128(uint32_t addr) {
    uint4 r;
    asm volatile("ld.shared.v4.b32 {%0,%1,%2,%3}, [%4];"
                 : "=r"(r.x), "=r"(r.y), "=r"(r.z), "=r"(r.w) : "r"(addr));
    return r;
}
__device__ __forceinline__ void mma_f16(float* c, uint32_t a0, uint32_t a1, uint32_t a2,
                                        uint32_t a3, uint32_t b0, uint32_t b1) {
    asm volatile(
        "mma.sync.aligned.m16n8k16.row.col.f32.f16.f16.f32 "
        "{%0,%1,%2,%3}, {%4,%5,%6,%7}, {%8,%9}, {%0,%1,%2,%3};"
        : "+f"(c[0]), "+f"(c[1]), "+f"(c[2]), "+f"(c[3])
        : "r"(a0), "r"(a1), "r"(a2), "r"(a3), "r"(b0), "r"(b1));
}
// store half2 into interleaved A layout at logical col c (even)
// within 32-col group (64B): phys half = 8t + 4q + 2s (+e), t=(c&7)>>1, s=(c>>3)&1, q=(c>>4)&1
__device__ __forceinline__ void sts_h2(uint32_t a_u32, int row, int c, float f0, float f1) {
    int w = c & 31;
    int t = (w & 7) >> 1, s = (w >> 3) & 1, q = (w >> 4) & 1;
    uint32_t byte = (uint32_t)(row * ASTR + (c >> 5) * 64 + (8 * t + 4 * q + 2 * s) * 2);
    __half2 h = __floats2half2_rn(f0, f1);
    asm volatile("st.shared.b32 [%0], %1;" :: "r"(a_u32 + byte), "r"(*(uint32_t*)&h));
}

// ---------------- weight permute: gmem image in per-fragment order (fp16) ----
// halves idx i: chunk(16 k-rows) -> wn slice -> (p,lane,j8)
//   ni = 2p + (j8>>2); k = chunk*16 + 2t + 8*((j8>>1)&1) + (j8&1); n = wn*(N/4)+ni*8+g
__device__ __forceinline__ void permute_h(const float* __restrict__ W, __half* __restrict__ dst,
                                          int i, int N) {
    int chunk = i / (16 * N);
    int r = i - chunk * 16 * N;
    int wn = r / (4 * N);
    int r2 = r - wn * 4 * N;
    int p = r2 >> 8;
    int lane = (r2 >> 3) & 31;
    int j8 = r2 & 7;
    int g = lane >> 2, t = lane & 3;
    int ni = 2 * p + (j8 >> 2);
    int k = chunk * 16 + 2 * t + 8 * ((j8 >> 1) & 1) + (j8 & 1);
    int n = wn * (N / 4) + ni * 8 + g;
    dst[i] = __float2half_rn(W[(size_t)k * N + n]);
}

__global__ void prep_kernel(const float* __restrict__ w1,
                            const float* __restrict__ w2,
                            const float* __restrict__ w3) {
    int b = blockIdx.x;
    if (b < 3125) {  // zero g_agg (800000 float4)
        int idx = b * 256 + threadIdx.x;
        reinterpret_cast<float4*>(g_agg)[idx] = make_float4(0.f, 0.f, 0.f, 0.f);
    } else {
        int i = (b - 3125) * 256 + threadIdx.x;
        if (i < 65536)        permute_h(w1, g_w1h, i, 256);
        else if (i < 131072)  permute_h(w2, g_w2h, i - 65536, 256);
        else                  permute_h(w3, g_w3h, i - 131072, 128);
    }
}

// ---------------- scatter via TMA bulk reduction ----------------
__global__ __launch_bounds__(256) void scatter_kernel(const float* __restrict__ edge_attr,
                                                      const int* __restrict__ col) {
    __shared__ float se[EPB * 64];
    __shared__ int   sc[EPB];
    const int tid = threadIdx.x;
    const long e0 = (long)blockIdx.x * EPB;

    if (tid < EPB) sc[tid] = col[e0 + tid];
    uint32_t sbase = (uint32_t)__cvta_generic_to_shared(se);
#pragma unroll
    for (int i = 0; i < 8; i++) {
        int l4 = tid + i * 256;
        cp16(sbase + l4 * 16, edge_attr + e0 * 64 + l4 * 4);
    }
    asm volatile("cp.async.commit_group;");
    asm volatile("cp.async.wait_group 0;");
    __syncthreads();

    if (tid < EPB) {
        float* dst = g_agg + (size_t)sc[tid] * 64;
        asm volatile("cp.reduce.async.bulk.global.shared::cta.bulk_group.add.f32 [%0], [%1], %2;"
                     :: "l"(dst), "r"(sbase + tid * 256), "r"(256) : "memory");
        asm volatile("cp.async.bulk.commit_group;");
        asm volatile("cp.async.bulk.wait_group 0;");
    }
}

// ---------------- fused MLP layer, fp16 m16n8k16, barrier-free k-loop ----------
// 8 warps: wm = warp&1 (2 x 32 rows), wn = warp>>1 (4 x N/4 cols)
template <int N, bool RELU, bool TOGMEM>
__device__ __forceinline__ void mlp_layer(
    uint32_t a_u32, uint32_t wbw_u32, const __half* __restrict__ Wg,
    const float* __restrict__ bias, float* __restrict__ outg, int m0,
    int wm, int wn, int g, int t, int lane)
{
    constexpr int TW = N / 4;
    constexpr int NI = N / 32;
    constexpr int NP = NI / 2;
    constexpr int CHUNKH = 16 * N;   // halves per 16-k chunk (all warps)
    constexpr int SLICEH = 4 * N;    // halves per warp slice per chunk

    float acc[2][NI][4] = {};
    const __half* wsrc = Wg + wn * SLICEH + lane * 8;

#define ISSUE(c) do {                                                        \
        const __half* _s = wsrc + (size_t)(c) * CHUNKH;                      \
        uint32_t _d = wbw_u32 + (uint32_t)((c) % 3) * 2048 + lane * 16;      \
        _Pragma("unroll")                                                    \
        for (int _p = 0; _p < NP; _p++) cp16(_d + _p * 512, _s + _p * 256);  \
        asm volatile("cp.async.commit_group;");                              \
    } while (0)

    ISSUE(0);
    ISSUE(1);
    uint4 av[2][2];
    const uint32_t arow = a_u32 + (uint32_t)((wm * 32 + g) * ASTR + t * 16);

#pragma unroll
    for (int kt = 0; kt < 16; kt++) {
        if (kt < 15) asm volatile("cp.async.wait_group 1;");
        else         asm volatile("cp.async.wait_group 0;");
        const int q = kt & 1;
        if (q == 0) {
#pragma unroll
            for (int mi = 0; mi < 2; mi++)
#pragma unroll
                for (int rh = 0; rh < 2; rh++)
                    av[mi][rh] = lds128(arow + (mi * 16 + rh * 8) * ASTR + (kt >> 1) * 64);
        }
        uint32_t a0[2], a1[2], a2[2], a3[2];
#pragma unroll
        for (int mi = 0; mi < 2; mi++) {
            a0[mi] = q ? av[mi][0].z : av[mi][0].x;
            a1[mi] = q ? av[mi][1].z : av[mi][1].x;
            a2[mi] = q ? av[mi][0].w : av[mi][0].y;
            a3[mi] = q ? av[mi][1].w : av[mi][1].y;
        }
        uint32_t wb = wbw_u32 + (uint32_t)(kt % 3) * 2048 + lane * 16;
#pragma unroll
        for (int p = 0; p < NP; p++) {
            uint4 bv = lds128(wb + p * 512);
            mma_f16(acc[0][2 * p],     a0[0], a1[0], a2[0], a3[0], bv.x, bv.y);
            mma_f16(acc[1][2 * p],     a0[1], a1[1], a2[1], a3[1], bv.x, bv.y);
            mma_f16(acc[0][2 * p + 1], a0[0], a1[0], a2[0], a3[0], bv.z, bv.w);
            mma_f16(acc[1][2 * p + 1], a0[1], a1[1], a2[1], a3[1], bv.z, bv.w);
        }
        if (kt + 2 < 16) ISSUE(kt + 2);
    }
#undef ISSUE
    __syncthreads();  // all warps done reading A before epilogue rewrites it

    // epilogue: bias + leaky (+ fp16 round into A) or fp32 to gmem
#pragma unroll
    for (int mi = 0; mi < 2; mi++) {
#pragma unroll
        for (int ni = 0; ni < NI; ni++) {
            int c = wn * TW + ni * 8 + 2 * t;
            float bv0 = bias[c], bv1 = bias[c + 1];
            float v0 = acc[mi][ni][0] + bv0;
            float v1 = acc[mi][ni][1] + bv1;
            float v2 = acc[mi][ni][2] + bv0;
            float v3 = acc[mi][ni][3] + bv1;
            if (RELU) {
                v0 = (v0 >= 0.f) ? v0 : 0.01f * v0;
                v1 = (v1 >= 0.f) ? v1 : 0.01f * v1;
                v2 = (v2 >= 0.f) ? v2 : 0.01f * v2;
                v3 = (v3 >= 0.f) ? v3 : 0.01f * v3;
            }
            int row = wm * 32 + mi * 16 + g;
            if (TOGMEM) {
                int gm0 = m0 + row, gm1 = gm0 + 8;
                if (gm0 < N_NODES)
                    *reinterpret_cast<float2*>(outg + (size_t)gm0 * N + c) = make_float2(v0, v1);
                if (gm1 < N_NODES)
                    *reinterpret_cast<float2*>(outg + (size_t)gm1 * N + c) = make_float2(v2, v3);
            } else {
                sts_h2(a_u32, row,     c, v0, v1);
                sts_h2(a_u32, row + 8, c, v2, v3);
            }
        }
    }
    if (!TOGMEM) __syncthreads();
}

// ---------------- fused kernel: h0 build + 3 layers ----------------
__global__ __launch_bounds__(THREADS, 2) void fused_mlp_kernel(
    const float* __restrict__ x, const float* __restrict__ u,
    const int* __restrict__ batch,
    const float* __restrict__ b1, const float* __restrict__ b2,
    const float* __restrict__ b3, float* __restrict__ out) {
    extern __shared__ char smem_raw[];
    __shared__ int s_batch[BM];

    const int tid = threadIdx.x, lane = tid & 31, warp = tid >> 5;
    const int wm = warp & 1, wn = warp >> 1;
    const int g = lane >> 2, t = lane & 3;
    const int m0 = blockIdx.x * BM;

    const uint32_t a_u32 = (uint32_t)__cvta_generic_to_shared(smem_raw);
    const uint32_t wbw_u32 = a_u32 + BM * ASTR + warp * 6144;  // per-warp 3x2KB ring

    if (tid < BM) {
        int gm = m0 + tid;
        s_batch[tid] = (gm < N_NODES) ? batch[gm] : 0;
    }
    // h0 cols [0,128): x  (2048 float4)
#pragma unroll
    for (int i = 0; i < 8; i++) {
        int idx = tid + i * THREADS;
        int row = idx >> 5, c4 = idx & 31;
        int gm = m0 + row;
        float4 v = make_float4(0.f, 0.f, 0.f, 0.f);
        if (gm < N_NODES) v = *reinterpret_cast<const float4*>(x + (size_t)gm * 128 + c4 * 4);
        sts_h2(a_u32, row, 4 * c4,     v.x, v.y);
        sts_h2(a_u32, row, 4 * c4 + 2, v.z, v.w);
    }
    // h0 cols [128,192): agg  (1024 float4)
#pragma unroll
    for (int i = 0; i < 4; i++) {
        int idx = tid + i * THREADS;
        int row = idx >> 4, c4 = idx & 15;
        int gm = m0 + row;
        float4 v = make_float4(0.f, 0.f, 0.f, 0.f);
        if (gm < N_NODES) v = *reinterpret_cast<const float4*>(g_agg + (size_t)gm * 64 + c4 * 4);
        sts_h2(a_u32, row, 128 + 4 * c4,     v.x, v.y);
        sts_h2(a_u32, row, 128 + 4 * c4 + 2, v.z, v.w);
    }
    __syncthreads();  // s_batch ready
    // h0 cols [192,256): u[batch]  (1024 float4)
#pragma unroll
    for (int i = 0; i < 4; i++) {
        int idx = tid + i * THREADS;
        int row = idx >> 4, c4 = idx & 15;
        float4 v = *reinterpret_cast<const float4*>(u + (size_t)s_batch[row] * 64 + c4 * 4);
        sts_h2(a_u32, row, 192 + 4 * c4,     v.x, v.y);
        sts_h2(a_u32, row, 192 + 4 * c4 + 2, v.z, v.w);
    }
    __syncthreads();  // h0 ready

    mlp_layer<256, true,  false>(a_u32, wbw_u32, g_w1h, b1, nullptr, m0, wm, wn, g, t, lane);
    mlp_layer<256, true,  false>(a_u32, wbw_u32, g_w2h, b2, nullptr, m0, wm, wn, g, t, lane);
    mlp_layer<128, false, true >(a_u32, wbw_u32, g_w3h, b3, out,     m0, wm, wn, g, t, lane);
}

// ---------------- launch ----------------
extern "C" void kernel_launch(void* const* d_in, const int* in_sizes, int n_in,
                              void* d_out, int out_size) {
    const float* x          = (const float*)d_in[0];
    const int*   edge_index = (const int*)d_in[1];
    const float* edge_attr  = (const float*)d_in[2];
    const float* u          = (const float*)d_in[3];
    const int*   batch      = (const int*)d_in[4];
    const float* w1         = (const float*)d_in[5];
    const float* b1         = (const float*)d_in[6];
    const float* w2         = (const float*)d_in[7];
    const float* b2         = (const float*)d_in[8];
    const float* w3         = (const float*)d_in[9];
    const float* b3         = (const float*)d_in[10];
    float* out = (float*)d_out;

    const int SMEM_BYTES = BM * ASTR + 8 * 6144;  // 36864 + 49152 = 86016 -> 2 CTAs/SM
    static bool attr_set = false;
    if (!attr_set) {
        cudaFuncSetAttribute(fused_mlp_kernel,
                             cudaFuncAttributeMaxDynamicSharedMemorySize, SMEM_BYTES);
        attr_set = true;
    }

    prep_kernel<<<3125 + 640, 256>>>(w1, w2, w3);
    scatter_kernel<<<N_EDGES / EPB, 256>>>(edge_attr, edge_index + N_EDGES);

    fused_mlp_kernel<<<(N_NODES + BM - 1) / BM, THREADS, SMEM_BYTES>>>(
        x, u, batch, b1, b2, b3, out);
}

// round 9
// speedup vs baseline: 2.8981x; 1.0419x over previous
#include <cuda_runtime.h>
#include <cuda_fp16.h>
#include <cstdint>

#define N_NODES  50000
#define N_EDGES  800000
#define BM       64
#define THREADS  256
#define ASTR     576     // A row stride bytes: 16B-aligned; /4=144 ≡16 mod 32 -> conflict-free LDS.128

// ---------------- device scratch (no allocs allowed; zero-initialized at load) ----
__device__ float  g_agg[N_NODES * 64];
__device__ __half g_w1h[256 * 256];
__device__ __half g_w2h[256 * 256];
__device__ __half g_w3h[256 * 128];

// ---------------- helpers ----------------
__device__ __forceinline__ void cp16(uint32_t smem_dst, const void* gsrc) {
    asm volatile("cp.async.cg.shared.global [%0], [%1], 16;" :: "r"(smem_dst), "l"(gsrc));
}
__device__ __forceinline__ uint4 lds128(uint32_t addr) {
    uint4 r;
    asm volatile("ld.shared.v4.b32 {%0,%1,%2,%3}, [%4];"
                 : "=r"(r.x), "=r"(r.y), "=r"(r.z), "=r"(r.w) : "r"(addr));
    return r;
}
__device__ __forceinline__ void mma_f16(float* c, uint32_t a0, uint32_t a1, uint32_t a2,
                                        uint32_t a3, uint32_t b0, uint32_t b1) {
    asm volatile(
        "mma.sync.aligned.m16n8k16.row.col.f32.f16.f16.f32 "
        "{%0,%1,%2,%3}, {%4,%5,%6,%7}, {%8,%9}, {%0,%1,%2,%3};"
        : "+f"(c[0]), "+f"(c[1]), "+f"(c[2]), "+f"(c[3])
        : "r"(a0), "r"(a1), "r"(a2), "r"(a3), "r"(b0), "r"(b1));
}
// store half2 into interleaved A layout at logical col c (even)
__device__ __forceinline__ void sts_h2(uint32_t a_u32, int row, int c, float f0, float f1) {
    int w = c & 31;
    int t = (w & 7) >> 1, s = (w >> 3) & 1, q = (w >> 4) & 1;
    uint32_t byte = (uint32_t)(row * ASTR + (c >> 5) * 64 + (8 * t + 4 * q + 2 * s) * 2);
    __half2 h = __floats2half2_rn(f0, f1);
    asm volatile("st.shared.b32 [%0], %1;" :: "r"(a_u32 + byte), "r"(*(uint32_t*)&h));
}

// ---------------- weight permute: gmem image in per-fragment order (fp16) ----
__device__ __forceinline__ void permute_h(const float* __restrict__ W, __half* __restrict__ dst,
                                          int i, int N) {
    int chunk = i / (16 * N);
    int r = i - chunk * 16 * N;
    int wn = r / (4 * N);
    int r2 = r - wn * 4 * N;
    int p = r2 >> 8;
    int lane = (r2 >> 3) & 31;
    int j8 = r2 & 7;
    int g = lane >> 2, t = lane & 3;
    int ni = 2 * p + (j8 >> 2);
    int k = chunk * 16 + 2 * t + 8 * ((j8 >> 1) & 1) + (j8 & 1);
    int n = wn * (N / 4) + ni * 8 + g;
    dst[i] = __float2half_rn(W[(size_t)k * N + n]);
}

// ---------------- scatter (warp-autonomous) + weight permute, one launch ------
#define SCAT_BLOCKS (N_EDGES / 128)   // 6250
__global__ __launch_bounds__(256) void scatter_prep_kernel(
    const float* __restrict__ edge_attr, const int* __restrict__ col,
    const float* __restrict__ w1, const float* __restrict__ w2,
    const float* __restrict__ w3) {
    int b = blockIdx.x;
    if (b < SCAT_BLOCKS) {
        __shared__ float se[128 * 64];   // 32KB
        const int tid = threadIdx.x, lane = tid & 31, warp = tid >> 5;
        const long e0 = (long)b * 128 + warp * 16;   // this warp's 16 edges
        const float* src = edge_attr + e0 * 64;
        const uint32_t sb = (uint32_t)__cvta_generic_to_shared(se) + warp * 4096;

        // 4KB coalesced staging: 8 cp16 per lane
#pragma unroll
        for (int j = 0; j < 8; j++)
            cp16(sb + (j * 32 + lane) * 16, src + (j * 32 + lane) * 4);
        asm volatile("cp.async.commit_group;");
        asm volatile("cp.async.wait_group 0;");
        __syncwarp();
        asm volatile("fence.proxy.async.shared::cta;" ::: "memory");

        // each lane reduces a 128B half-edge
        int eo = lane >> 1, half = lane & 1;
        int node = __ldg(col + e0 + eo);
        float* dst = g_agg + (size_t)node * 64 + half * 32;
        asm volatile("cp.reduce.async.bulk.global.shared::cta.bulk_group.add.f32 [%0], [%1], %2;"
                     :: "l"(dst), "r"(sb + eo * 256 + half * 128), "r"(128) : "memory");
        asm volatile("cp.async.bulk.commit_group;");
        asm volatile("cp.async.bulk.wait_group 0;");
    } else {
        int i = (b - SCAT_BLOCKS) * 256 + threadIdx.x;   // 640 blocks -> 163840
        if (i < 65536)        permute_h(w1, g_w1h, i, 256);
        else if (i < 131072)  permute_h(w2, g_w2h, i - 65536, 256);
        else                  permute_h(w3, g_w3h, i - 131072, 128);
    }
}

// ---------------- fused MLP layer, fp16 m16n8k16, barrier-free k-loop ----------
template <int N, bool RELU, bool TOGMEM>
__device__ __forceinline__ void mlp_layer(
    uint32_t a_u32, uint32_t wbw_u32, const __half* __restrict__ Wg,
    const float* __restrict__ bias, float* __restrict__ outg, int m0,
    int wm, int wn, int g, int t, int lane)
{
    constexpr int TW = N / 4;
    constexpr int NI = N / 32;
    constexpr int NP = NI / 2;
    constexpr int CHUNKH = 16 * N;
    constexpr int SLICEH = 4 * N;

    float acc[2][NI][4] = {};
    const __half* wsrc = Wg + wn * SLICEH + lane * 8;

#define ISSUE(c) do {                                                        \
        const __half* _s = wsrc + (size_t)(c) * CHUNKH;                      \
        uint32_t _d = wbw_u32 + (uint32_t)((c) % 3) * 2048 + lane * 16;      \
        _Pragma("unroll")                                                    \
        for (int _p = 0; _p < NP; _p++) cp16(_d + _p * 512, _s + _p * 256);  \
        asm volatile("cp.async.commit_group;");                              \
    } while (0)

    ISSUE(0);
    ISSUE(1);
    uint4 av[2][2];
    const uint32_t arow = a_u32 + (uint32_t)((wm * 32 + g) * ASTR + t * 16);

#pragma unroll
    for (int kt = 0; kt < 16; kt++) {
        if (kt < 15) asm volatile("cp.async.wait_group 1;");
        else         asm volatile("cp.async.wait_group 0;");
        const int q = kt & 1;
        if (q == 0) {
#pragma unroll
            for (int mi = 0; mi < 2; mi++)
#pragma unroll
                for (int rh = 0; rh < 2; rh++)
                    av[mi][rh] = lds128(arow + (mi * 16 + rh * 8) * ASTR + (kt >> 1) * 64);
        }
        uint32_t a0[2], a1[2], a2[2], a3[2];
#pragma unroll
        for (int mi = 0; mi < 2; mi++) {
            a0[mi] = q ? av[mi][0].z : av[mi][0].x;
            a1[mi] = q ? av[mi][1].z : av[mi][1].x;
            a2[mi] = q ? av[mi][0].w : av[mi][0].y;
            a3[mi] = q ? av[mi][1].w : av[mi][1].y;
        }
        uint32_t wb = wbw_u32 + (uint32_t)(kt % 3) * 2048 + lane * 16;
#pragma unroll
        for (int p = 0; p < NP; p++) {
            uint4 bv = lds128(wb + p * 512);
            mma_f16(acc[0][2 * p],     a0[0], a1[0], a2[0], a3[0], bv.x, bv.y);
            mma_f16(acc[1][2 * p],     a0[1], a1[1], a2[1], a3[1], bv.x, bv.y);
            mma_f16(acc[0][2 * p + 1], a0[0], a1[0], a2[0], a3[0], bv.z, bv.w);
            mma_f16(acc[1][2 * p + 1], a0[1], a1[1], a2[1], a3[1], bv.z, bv.w);
        }
        if (kt + 2 < 16) ISSUE(kt + 2);
    }
#undef ISSUE
    __syncthreads();  // all warps done reading A before epilogue rewrites it

#pragma unroll
    for (int mi = 0; mi < 2; mi++) {
#pragma unroll
        for (int ni = 0; ni < NI; ni++) {
            int c = wn * TW + ni * 8 + 2 * t;
            float bv0 = bias[c], bv1 = bias[c + 1];
            float v0 = acc[mi][ni][0] + bv0;
            float v1 = acc[mi][ni][1] + bv1;
            float v2 = acc[mi][ni][2] + bv0;
            float v3 = acc[mi][ni][3] + bv1;
            if (RELU) {
                v0 = (v0 >= 0.f) ? v0 : 0.01f * v0;
                v1 = (v1 >= 0.f) ? v1 : 0.01f * v1;
                v2 = (v2 >= 0.f) ? v2 : 0.01f * v2;
                v3 = (v3 >= 0.f) ? v3 : 0.01f * v3;
            }
            int row = wm * 32 + mi * 16 + g;
            if (TOGMEM) {
                int gm0 = m0 + row, gm1 = gm0 + 8;
                if (gm0 < N_NODES)
                    *reinterpret_cast<float2*>(outg + (size_t)gm0 * N + c) = make_float2(v0, v1);
                if (gm1 < N_NODES)
                    *reinterpret_cast<float2*>(outg + (size_t)gm1 * N + c) = make_float2(v2, v3);
            } else {
                sts_h2(a_u32, row,     c, v0, v1);
                sts_h2(a_u32, row + 8, c, v2, v3);
            }
        }
    }
    if (!TOGMEM) __syncthreads();
}

// ---------------- fused kernel: h0 build + re-zero agg + 3 layers --------------
__global__ __launch_bounds__(THREADS, 2) void fused_mlp_kernel(
    const float* __restrict__ x, const float* __restrict__ u,
    const int* __restrict__ batch,
    const float* __restrict__ b1, const float* __restrict__ b2,
    const float* __restrict__ b3, float* __restrict__ out) {
    extern __shared__ char smem_raw[];
    __shared__ int s_batch[BM];

    const int tid = threadIdx.x, lane = tid & 31, warp = tid >> 5;
    const int wm = warp & 1, wn = warp >> 1;
    const int g = lane >> 2, t = lane & 3;
    const int m0 = blockIdx.x * BM;

    const uint32_t a_u32 = (uint32_t)__cvta_generic_to_shared(smem_raw);
    const uint32_t wbw_u32 = a_u32 + BM * ASTR + warp * 6144;  // per-warp 3x2KB ring

    if (tid < BM) {
        int gm = m0 + tid;
        s_batch[tid] = (gm < N_NODES) ? batch[gm] : 0;
    }
    // h0 cols [0,128): x  (2048 float4)
#pragma unroll
    for (int i = 0; i < 8; i++) {
        int idx = tid + i * THREADS;
        int row = idx >> 5, c4 = idx & 31;
        int gm = m0 + row;
        float4 v = make_float4(0.f, 0.f, 0.f, 0.f);
        if (gm < N_NODES) v = *reinterpret_cast<const float4*>(x + (size_t)gm * 128 + c4 * 4);
        sts_h2(a_u32, row, 4 * c4,     v.x, v.y);
        sts_h2(a_u32, row, 4 * c4 + 2, v.z, v.w);
    }
    // h0 cols [128,192): agg  (1024 float4)
#pragma unroll
    for (int i = 0; i < 4; i++) {
        int idx = tid + i * THREADS;
        int row = idx >> 4, c4 = idx & 15;
        int gm = m0 + row;
        float4 v = make_float4(0.f, 0.f, 0.f, 0.f);
        if (gm < N_NODES) v = *reinterpret_cast<const float4*>(g_agg + (size_t)gm * 64 + c4 * 4);
        sts_h2(a_u32, row, 128 + 4 * c4,     v.x, v.y);
        sts_h2(a_u32, row, 128 + 4 * c4 + 2, v.z, v.w);
    }
    __syncthreads();  // s_batch ready
    // h0 cols [192,256): u[batch]  (1024 float4)
#pragma unroll
    for (int i = 0; i < 4; i++) {
        int idx = tid + i * THREADS;
        int row = idx >> 4, c4 = idx & 15;
        float4 v = *reinterpret_cast<const float4*>(u + (size_t)s_batch[row] * 64 + c4 * 4);
        sts_h2(a_u32, row, 192 + 4 * c4,     v.x, v.y);
        sts_h2(a_u32, row, 192 + 4 * c4 + 2, v.z, v.w);
    }
    // re-zero this block's agg rows for the next graph replay (agg already
    // consumed into smem above; __device__ globals start zeroed at load).
#pragma unroll
    for (int i = 0; i < 4; i++) {
        int idx = tid + i * THREADS;   // 1024 float4 = 64 rows x 64 floats
        int row = idx >> 4, c4 = idx & 15;
        int gm = m0 + row;
        if (gm < N_NODES)
            *reinterpret_cast<float4*>(g_agg + (size_t)gm * 64 + c4 * 4) =
                make_float4(0.f, 0.f, 0.f, 0.f);
    }
    __syncthreads();  // h0 ready

    mlp_layer<256, true,  false>(a_u32, wbw_u32, g_w1h, b1, nullptr, m0, wm, wn, g, t, lane);
    mlp_layer<256, true,  false>(a_u32, wbw_u32, g_w2h, b2, nullptr, m0, wm, wn, g, t, lane);
    mlp_layer<128, false, true >(a_u32, wbw_u32, g_w3h, b3, out,     m0, wm, wn, g, t, lane);
}

// ---------------- launch ----------------
extern "C" void kernel_launch(void* const* d_in, const int* in_sizes, int n_in,
                              void* d_out, int out_size) {
    const float* x          = (const float*)d_in[0];
    const int*   edge_index = (const int*)d_in[1];
    const float* edge_attr  = (const float*)d_in[2];
    const float* u          = (const float*)d_in[3];
    const int*   batch      = (const int*)d_in[4];
    const float* w1         = (const float*)d_in[5];
    const float* b1         = (const float*)d_in[6];
    const float* w2         = (const float*)d_in[7];
    const float* b2         = (const float*)d_in[8];
    const float* w3         = (const float*)d_in[9];
    const float* b3         = (const float*)d_in[10];
    float* out = (float*)d_out;

    const int SMEM_BYTES = BM * ASTR + 8 * 6144;  // 36864 + 49152 = 86016 -> 2 CTAs/SM
    static bool attr_set = false;
    if (!attr_set) {
        cudaFuncSetAttribute(fused_mlp_kernel,
                             cudaFuncAttributeMaxDynamicSharedMemorySize, SMEM_BYTES);
        attr_set = true;
    }

    scatter_prep_kernel<<<SCAT_BLOCKS + 640, 256>>>(edge_attr, edge_index + N_EDGES,
                                                    w1, w2, w3);
    fused_mlp_kernel<<<(N_NODES + BM - 1) / BM, THREADS, SMEM_BYTES>>>(
        x, u, batch, b1, b2, b3, out);
}